// round 6
// baseline (speedup 1.0000x reference)
#include <cuda_runtime.h>
#include <math.h>

#define V_   1000
#define H_   512
#define D_   512
#define NH   8
#define DK   64
#define MEM_ 512
#define BS   128
#define TMAX 160
#define NBLK 128
#define NFC  125            // fc tiles of 8 outputs: 125*8 = 1000

#define OUT_H_OFF (TMAX*BS*V_)                 // 20,480,000
#define OUT_S_OFF (OUT_H_OFF + TMAX*BS*H_)     // 30,965,760

// ---------------- device scratch (static; no allocations) ----------------
__device__ float g_kt[(size_t)BS*NH*DK*MEM_];  // K transposed: [b][h][d][m]
__device__ float g_vp[(size_t)BS*NH*MEM_*DK];  // V: [b][h][m][d]
__device__ float g_h2[2][BS*H_];               // double-buffered hidden
__device__ float g_q [BS*D_];
__device__ float g_ctx[BS*D_];
__device__ float g_pv[NFC*BS];                 // fc partial argmax values
__device__ int   g_pi[NFC*BS];                 // fc partial argmax indices
__device__ unsigned g_bar_count;
__device__ volatile unsigned g_bar_gen;

// ---------------- init ----------------
__global__ void init_kernel() {
    int i = blockIdx.x * blockDim.x + threadIdx.x;
    int total = 2 * BS * H_;
    for (; i < total; i += gridDim.x * blockDim.x)
        ((float*)g_h2)[i] = 0.f;
}

// ---------------- KV projection (once). K written transposed. ----------------
__global__ void __launch_bounds__(256) kvproj_kernel(
    const float* __restrict__ memory, const float* __restrict__ Wk, const float* __restrict__ bk,
    const float* __restrict__ Wv, const float* __restrict__ bv)
{
    __shared__ float Xs[64][17];
    __shared__ float Ks[64][17];
    __shared__ float Vs[64][17];
    int m0 = blockIdx.x * 64, n0 = blockIdx.y * 64, b = blockIdx.z;
    int tid = threadIdx.x;
    int tn = tid & 15, tm = tid >> 4;
    float accK[4][4] = {}, accV[4][4] = {};

    for (int k0 = 0; k0 < D_; k0 += 16) {
        #pragma unroll
        for (int i = 0; i < 4; i++) {
            int e = tid + i * 256;
            int kk = e & 15, mm = e >> 4;
            Xs[mm][kk] = memory[((size_t)(m0 + mm) * BS + b) * D_ + k0 + kk];
            Ks[mm][kk] = Wk[(size_t)(n0 + mm) * D_ + k0 + kk];
            Vs[mm][kk] = Wv[(size_t)(n0 + mm) * D_ + k0 + kk];
        }
        __syncthreads();
        #pragma unroll
        for (int kk = 0; kk < 16; kk++) {
            float xv[4], kw[4], vw[4];
            #pragma unroll
            for (int i = 0; i < 4; i++) xv[i] = Xs[tm * 4 + i][kk];
            #pragma unroll
            for (int j = 0; j < 4; j++) { kw[j] = Ks[tn * 4 + j][kk]; vw[j] = Vs[tn * 4 + j][kk]; }
            #pragma unroll
            for (int i = 0; i < 4; i++)
                #pragma unroll
                for (int j = 0; j < 4; j++) {
                    accK[i][j] = fmaf(xv[i], kw[j], accK[i][j]);
                    accV[i][j] = fmaf(xv[i], vw[j], accV[i][j]);
                }
        }
        __syncthreads();
    }
    #pragma unroll
    for (int i = 0; i < 4; i++) {
        int m = m0 + tm * 4 + i;
        #pragma unroll
        for (int j = 0; j < 4; j++) {
            int n = n0 + tn * 4 + j;
            int h = n >> 6, d = n & 63;
            g_kt[(((size_t)b * NH + h) * DK + d) * MEM_ + m]  = accK[i][j] + bk[n];
            g_vp[(((size_t)b * NH + h) * MEM_ + m) * DK + d]  = accV[i][j] + bv[n];
        }
    }
}

// ---------------- shared-memory overlays for the persistent kernel ----------------
struct QSm  { float Xs[32][133]; float Ws[4][33]; int toks[BS]; };
struct AttSm{ float qs[D_]; float sc[NH][MEM_]; float pctx[4][128][4];
              float wred[16], wred2[16], invs[NH]; };
struct GruSm{ float Xs[2][32][133]; float Ws[2][12][33]; float red[4][64][6]; };
struct FcSm { float Xs[32][133]; float Ws[8][33]; float apv[4][BS]; int api[4][BS]; };

#define SMEM_BYTES 43392   // >= sizeof(GruSm) = 43360

__device__ __forceinline__ void grid_bar() {
    __syncthreads();
    if (threadIdx.x == 0) {
        unsigned gen = g_bar_gen;
        __threadfence();
        unsigned ticket = atomicAdd(&g_bar_count, 1u);
        if (ticket == gridDim.x - 1) {
            g_bar_count = 0;
            __threadfence();
            g_bar_gen = gen + 1;
        } else {
            while (g_bar_gen == gen) __nanosleep(32);
            __threadfence();
        }
    }
    __syncthreads();
}

__device__ __forceinline__ float sigmoidf_(float x) { return 1.f / (1.f + expf(-x)); }

// ---------------- persistent decode kernel (whole 160-step loop) ----------------
__global__ void __launch_bounds__(512, 1) decode_kernel(
    const float* __restrict__ emb,  const float* __restrict__ Wq,  const float* __restrict__ bq,
    const float* __restrict__ Wih,  const float* __restrict__ Whh,
    const float* __restrict__ bih,  const float* __restrict__ bhh,
    const float* __restrict__ Wfc,  const float* __restrict__ bfc,
    const int*   __restrict__ lens, float* __restrict__ out)
{
    __shared__ __align__(16) unsigned char smbuf[SMEM_BYTES];
    const int bid = blockIdx.x;
    const int tid = threadIdx.x;

    for (int t = 0; t < TMAX; t++) {
        const float* hcur = g_h2[t & 1];
        float* hnext = g_h2[(t + 1) & 1];

        // ================= phase Q: toks + q = [emb[tok],h] @ Wq^T + bq =========
        {
            QSm& S = *(QSm*)smbuf;
            if (tid < BS) {
                int b = tid, bi = 0;
                if (t > 0) {
                    float bv = -3.4e38f;
                    for (int p = 0; p < NFC; p++) {
                        float v = g_pv[p * BS + b];
                        if (v > bv) { bv = v; bi = g_pi[p * BS + b]; }
                    }
                }
                S.toks[b] = bi;
            }
            __syncthreads();
            const int n = bid * 4 + (tid >> 7);     // 4 outputs per block
            const int b = tid & 127;
            float acc = 0.f;
            for (int k0 = 0; k0 < 2 * H_; k0 += 32) {
                #pragma unroll
                for (int i = 0; i < 8; i++) {       // stage X[32][128] transposed
                    int e = tid + i * 512;
                    int kk = e & 31, bb = e >> 5;
                    int j = k0 + kk;
                    S.Xs[kk][bb] = (j < H_) ? emb[(size_t)S.toks[bb] * H_ + j]
                                            : hcur[bb * H_ + (j - H_)];
                }
                if (tid < 128) {
                    int row = tid >> 5, kk = tid & 31;
                    S.Ws[row][kk] = Wq[(size_t)(bid * 4 + row) * (2 * H_) + k0 + kk];
                }
                __syncthreads();
                const float* wr = S.Ws[tid >> 7];
                #pragma unroll
                for (int kk = 0; kk < 32; kk++)
                    acc = fmaf(S.Xs[kk][b], wr[kk], acc);
                __syncthreads();
            }
            g_q[b * D_ + n] = acc + bq[n];
        }
        grid_bar();

        // ================= phase ATT: block = batch ==============================
        {
            AttSm& S = *(AttSm*)smbuf;
            S.qs[tid] = g_q[bid * D_ + tid];
            __syncthreads();

            // scores: head h = tid>>6, i = tid&63; m in {4i..4i+3, 256+4i..+3}
            {
                int h = tid >> 6, i = tid & 63;
                const float* kt = g_kt + (size_t)(bid * NH + h) * DK * MEM_;
                float4 a0 = {0,0,0,0}, a1 = {0,0,0,0};
                #pragma unroll 4
                for (int d = 0; d < DK; d++) {
                    float qv = S.qs[h * DK + d];
                    const float4* row = (const float4*)(kt + (size_t)d * MEM_);
                    float4 k0v = row[i];
                    float4 k1v = row[64 + i];
                    a0.x = fmaf(qv, k0v.x, a0.x); a0.y = fmaf(qv, k0v.y, a0.y);
                    a0.z = fmaf(qv, k0v.z, a0.z); a0.w = fmaf(qv, k0v.w, a0.w);
                    a1.x = fmaf(qv, k1v.x, a1.x); a1.y = fmaf(qv, k1v.y, a1.y);
                    a1.z = fmaf(qv, k1v.z, a1.z); a1.w = fmaf(qv, k1v.w, a1.w);
                }
                const float sc_ = 0.125f;
                float4 s0 = {a0.x*sc_, a0.y*sc_, a0.z*sc_, a0.w*sc_};
                float4 s1 = {a1.x*sc_, a1.y*sc_, a1.z*sc_, a1.w*sc_};
                *(float4*)&S.sc[h][4 * i]       = s0;
                *(float4*)&S.sc[h][256 + 4 * i] = s1;
            }
            __syncthreads();

            // softmax per head (64 threads/head)
            int h = tid >> 6, i = tid & 63;
            float mx = -3.4e38f;
            #pragma unroll
            for (int r = 0; r < 8; r++) mx = fmaxf(mx, S.sc[h][i + (r << 6)]);
            #pragma unroll
            for (int o = 16; o > 0; o >>= 1) mx = fmaxf(mx, __shfl_xor_sync(0xffffffffu, mx, o));
            if ((tid & 31) == 0) S.wred[tid >> 5] = mx;
            __syncthreads();
            float mh = fmaxf(S.wred[2 * h], S.wred[2 * h + 1]);

            float s = 0.f;
            #pragma unroll
            for (int r = 0; r < 8; r++) {
                int m = i + (r << 6);
                float e = expf(S.sc[h][m] - mh);
                S.sc[h][m] = e;
                s += e;
            }
            #pragma unroll
            for (int o = 16; o > 0; o >>= 1) s += __shfl_xor_sync(0xffffffffu, s, o);
            if ((tid & 31) == 0) S.wred2[tid >> 5] = s;
            __syncthreads();
            float inv = 1.f / (S.wred2[2 * h] + S.wred2[2 * h + 1]);
            if (i == 0) S.invs[h] = inv;
            __syncthreads();

            // scores output (mean over heads, masked)
            {
                float sm = 0.f;
                #pragma unroll
                for (int hh = 0; hh < NH; hh++) sm += S.sc[hh][tid] * S.invs[hh];
                sm *= 0.125f;
                int run = t < lens[bid];
                out[OUT_S_OFF + ((size_t)t * BS + bid) * MEM_ + tid] = run ? sm : 0.f;
            }

            // ctx: rep = tid>>7 covers m-chunk of 128; slot -> (h, 4 d's) float4
            {
                int rep = tid >> 7, slot = tid & 127;
                int ch = slot >> 4, d4 = (slot & 15) * 4;
                const float* vb = g_vp + ((size_t)(bid * NH + ch) * MEM_ + rep * 128) * DK + d4;
                const float* ph = &S.sc[ch][rep * 128];
                float4 a = {0,0,0,0};
                #pragma unroll 4
                for (int m = 0; m < 128; m++) {
                    float p = ph[m];
                    float4 v = *(const float4*)(vb + (size_t)m * DK);
                    a.x = fmaf(p, v.x, a.x); a.y = fmaf(p, v.y, a.y);
                    a.z = fmaf(p, v.z, a.z); a.w = fmaf(p, v.w, a.w);
                }
                __syncthreads();           // scores-out readers done with sc before reuse is irrelevant; protects pctx region ordering
                *(float4*)&S.pctx[rep][slot][0] = a;
            }
            __syncthreads();
            if (tid < 128) {
                int slot = tid, ch = slot >> 4, d4 = (slot & 15) * 4;
                float4 a0 = *(float4*)&S.pctx[0][slot][0];
                float4 a1 = *(float4*)&S.pctx[1][slot][0];
                float4 a2 = *(float4*)&S.pctx[2][slot][0];
                float4 a3 = *(float4*)&S.pctx[3][slot][0];
                float inv2 = S.invs[ch];
                float4 r;
                r.x = (a0.x + a1.x + a2.x + a3.x) * inv2;
                r.y = (a0.y + a1.y + a2.y + a3.y) * inv2;
                r.z = (a0.z + a1.z + a2.z + a3.z) * inv2;
                r.w = (a0.w + a1.w + a2.w + a3.w) * inv2;
                *(float4*)&g_ctx[bid * D_ + ch * DK + d4] = r;
            }
        }
        grid_bar();

        // ================= phase GRU (gate-triple tiling, fused activation) ======
        {
            GruSm& S = *(GruSm*)smbuf;
            const int j0 = bid * 4;
            const int kh = tid >> 8;              // 0: input path (ctx/Wih), 1: hidden path (h/Whh)
            const int r  = tid & 255;
            const int jj = r >> 6, bp = r & 63, b0 = bp * 2;
            const float* xsrc = kh ? hcur : g_ctx;
            const float* Wsrc = kh ? Whh  : Wih;
            float a[3][2] = {};
            for (int k0 = 0; k0 < H_; k0 += 32) {
                #pragma unroll
                for (int i = 0; i < 16; i++) {    // stage X[32][128] transposed (per half)
                    int e = r + i * 256;
                    int kk = e & 31, bb = e >> 5;
                    S.Xs[kh][kk][bb] = xsrc[bb * H_ + k0 + kk];
                }
                #pragma unroll
                for (int i = 0; i < 2; i++) {     // stage 12 weight rows
                    int e = r + i * 256;
                    if (e < 384) {
                        int row = e >> 5, kk = e & 31;
                        int g = row >> 2, jr = row & 3;
                        S.Ws[kh][row][kk] = Wsrc[((size_t)g * H_ + j0 + jr) * H_ + k0 + kk];
                    }
                }
                __syncthreads();
                #pragma unroll
                for (int kk = 0; kk < 32; kk++) {
                    float x0 = S.Xs[kh][kk][b0];
                    float x1 = S.Xs[kh][kk][b0 + 1];
                    #pragma unroll
                    for (int g = 0; g < 3; g++) {
                        float w = S.Ws[kh][g * 4 + jj][kk];
                        a[g][0] = fmaf(x0, w, a[g][0]);
                        a[g][1] = fmaf(x1, w, a[g][1]);
                    }
                }
                __syncthreads();
            }
            if (kh == 1) {
                #pragma unroll
                for (int g = 0; g < 3; g++) {
                    S.red[jj][bp][g * 2]     = a[g][0];
                    S.red[jj][bp][g * 2 + 1] = a[g][1];
                }
            }
            __syncthreads();
            if (kh == 0) {
                int j = j0 + jj;
                float bir = bih[j], biz = bih[j + H_], bin_ = bih[j + 2 * H_];
                float bhr = bhh[j], bhz = bhh[j + H_], bhn = bhh[j + 2 * H_];
                #pragma unroll
                for (int ib = 0; ib < 2; ib++) {
                    int b = b0 + ib;
                    float gir = a[0][ib] + bir;
                    float giz = a[1][ib] + biz;
                    float gin = a[2][ib] + bin_;
                    float ghr = S.red[jj][bp][0 * 2 + ib] + bhr;
                    float ghz = S.red[jj][bp][1 * 2 + ib] + bhz;
                    float ghn = S.red[jj][bp][2 * 2 + ib] + bhn;
                    float rr = sigmoidf_(gir + ghr);
                    float zz = sigmoidf_(giz + ghz);
                    float nn = tanhf(gin + rr * ghn);
                    float hold = hcur[b * H_ + j];
                    float hn = (1.f - zz) * nn + zz * hold;
                    hnext[b * H_ + j] = hn;
                    int run = t < lens[b];
                    out[OUT_H_OFF + ((size_t)t * BS + b) * H_ + j] = run ? hn : 0.f;
                }
            }
        }
        grid_bar();

        // ================= phase FC (+ partial argmax) ===========================
        if (bid < NFC) {
            FcSm& S = *(FcSm*)smbuf;
            const int n0 = bid * 8;
            const int tn = tid >> 7;             // 0..3, each handles 2 n
            const int b  = tid & 127;
            float acc0 = 0.f, acc1 = 0.f;
            for (int k0 = 0; k0 < H_; k0 += 32) {
                #pragma unroll
                for (int i = 0; i < 8; i++) {
                    int e = tid + i * 512;
                    int kk = e & 31, bb = e >> 5;
                    S.Xs[kk][bb] = hnext[bb * H_ + k0 + kk];
                }
                if (tid < 256) {
                    int row = tid >> 5, kk = tid & 31;
                    S.Ws[row][kk] = Wfc[(size_t)(n0 + row) * H_ + k0 + kk];
                }
                __syncthreads();
                const float* w0 = S.Ws[tn * 2];
                const float* w1 = S.Ws[tn * 2 + 1];
                #pragma unroll
                for (int kk = 0; kk < 32; kk++) {
                    float x = S.Xs[kk][b];
                    acc0 = fmaf(x, w0[kk], acc0);
                    acc1 = fmaf(x, w1[kk], acc1);
                }
                __syncthreads();
            }
            int na = n0 + tn * 2, nb = na + 1;
            float v0 = acc0 + bfc[na];
            float v1 = acc1 + bfc[nb];
            int run = t < lens[b];
            size_t ob = ((size_t)t * BS + b) * V_;
            out[ob + na] = run ? v0 : 0.f;
            out[ob + nb] = run ? v1 : 0.f;
            // local argmax over the 2 n's (first-occurrence: strictly-greater replaces)
            float lv = v0; int li = na;
            if (v1 > lv) { lv = v1; li = nb; }
            S.apv[tn][b] = lv;
            S.api[tn][b] = li;
            __syncthreads();
            if (tn == 0) {
                float bv = S.apv[0][b]; int bi = S.api[0][b];
                #pragma unroll
                for (int p = 1; p < 4; p++) {
                    float v = S.apv[p][b];
                    if (v > bv) { bv = v; bi = S.api[p][b]; }
                }
                g_pv[bid * BS + b] = bv;
                g_pi[bid * BS + b] = bi;
            }
        }
        grid_bar();
    }
}

// ---------------- launch ----------------
extern "C" void kernel_launch(void* const* d_in, const int* in_sizes, int n_in,
                              void* d_out, int out_size)
{
    const float* memory = (const float*)d_in[0];
    const float* emb    = (const float*)d_in[1];
    const float* Wq     = (const float*)d_in[2];
    const float* bq     = (const float*)d_in[3];
    const float* Wk     = (const float*)d_in[4];
    const float* bk     = (const float*)d_in[5];
    const float* Wv     = (const float*)d_in[6];
    const float* bv     = (const float*)d_in[7];
    const float* Wih    = (const float*)d_in[8];
    const float* Whh    = (const float*)d_in[9];
    const float* bih    = (const float*)d_in[10];
    const float* bhh    = (const float*)d_in[11];
    const float* Wfc    = (const float*)d_in[12];
    const float* bfc    = (const float*)d_in[13];
    const int*   lens   = (const int*)d_in[14];
    float* out = (float*)d_out;

    init_kernel<<<128, 256>>>();
    kvproj_kernel<<<dim3(MEM_ / 64, D_ / 64, BS), 256>>>(memory, Wk, bk, Wv, bv);
    decode_kernel<<<NBLK, 512>>>(emb, Wq, bq, Wih, Whh, bih, bhh, Wfc, bfc, lens, out);
}

// round 8
// speedup vs baseline: 1.0568x; 1.0568x over previous
#include <cuda_runtime.h>
#include <math.h>
#include <stdint.h>

#define V_   1000
#define H_   512
#define D_   512
#define NH   8
#define DK   64
#define MEM_ 512
#define BS   128
#define TMAX 160
#define NBLK 128
#define NFC  125            // fc tiles of 8 outputs: 125*8 = 1000

#define OUT_H_OFF (TMAX*BS*V_)                 // 20,480,000
#define OUT_S_OFF (OUT_H_OFF + TMAX*BS*H_)     // 30,965,760

// dynamic smem layout (bytes)
// [0, 44032)        : per-phase overlays (QSm / GruSm / FcSm / attention arrays)
// [44032, 44064)    : 4 mbarriers
// [44160, 175232)   : 4 x 32KB TMA ring buffers
#define OFF_QS     0
#define OFF_SC     2048
#define OFF_RED    18432
#define OFF_WRED   34816
#define OFF_WRED2  34880
#define OFF_INVS   34944
#define OFF_MBAR   44032
#define OFF_BUF    44160
#define CHUNK_B    32768
#define SMEM_TOTAL (OFF_BUF + 4*CHUNK_B)      // 175232

// ---------------- device scratch (static; no allocations) ----------------
__device__ float g_kt[(size_t)BS*NH*DK*MEM_];  // K transposed: [b][h][d][m]
__device__ float g_vp[(size_t)BS*NH*MEM_*DK];  // V: [b][h][m][d]
__device__ float g_h2[2][BS*H_];               // double-buffered hidden
__device__ float g_q [BS*D_];
__device__ float g_ctx[BS*D_];
__device__ float g_pv[NFC*BS];                 // fc partial argmax values
__device__ int   g_pi[NFC*BS];                 // fc partial argmax indices
__device__ unsigned g_bar_count;
__device__ volatile unsigned g_bar_gen;

// ---------------- PTX helpers ----------------
__device__ __forceinline__ unsigned s2u(const void* p) {
    return (unsigned)__cvta_generic_to_shared(p);
}
__device__ __forceinline__ void mbar_init(unsigned a, unsigned cnt) {
    asm volatile("mbarrier.init.shared.b64 [%0], %1;" :: "r"(a), "r"(cnt) : "memory");
}
__device__ __forceinline__ void mbar_expect_tx(unsigned a, unsigned bytes) {
    asm volatile("mbarrier.arrive.expect_tx.shared.b64 _, [%0], %1;"
                 :: "r"(a), "r"(bytes) : "memory");
}
__device__ __forceinline__ void mbar_wait(unsigned a, unsigned parity) {
    unsigned done;
    asm volatile(
        "{\n\t.reg .pred p;\n\t"
        "mbarrier.try_wait.parity.acquire.cta.shared::cta.b64 p, [%1], %2, 0x989680;\n\t"
        "selp.b32 %0, 1, 0, p;\n\t}"
        : "=r"(done) : "r"(a), "r"(parity) : "memory");
    while (!done) {
        asm volatile(
            "{\n\t.reg .pred p;\n\t"
            "mbarrier.try_wait.parity.acquire.cta.shared::cta.b64 p, [%1], %2, 0x989680;\n\t"
            "selp.b32 %0, 1, 0, p;\n\t}"
            : "=r"(done) : "r"(a), "r"(parity) : "memory");
    }
}
__device__ __forceinline__ void tma_g2s(unsigned dst, const void* src, unsigned bytes, unsigned mbar) {
    asm volatile(
        "cp.async.bulk.shared::cluster.global.mbarrier::complete_tx::bytes [%0], [%1], %2, [%3];"
        :: "r"(dst), "l"(src), "r"(bytes), "r"(mbar) : "memory");
}
__device__ __forceinline__ float sigmoidf_(float x) { return 1.f / (1.f + expf(-x)); }

// ---------------- init ----------------
__global__ void init_kernel() {
    int i = blockIdx.x * blockDim.x + threadIdx.x;
    int total = 2 * BS * H_;
    for (; i < total; i += gridDim.x * blockDim.x)
        ((float*)g_h2)[i] = 0.f;
}

// ---------------- KV projection (once). K written transposed. ----------------
__global__ void __launch_bounds__(256) kvproj_kernel(
    const float* __restrict__ memory, const float* __restrict__ Wk, const float* __restrict__ bk,
    const float* __restrict__ Wv, const float* __restrict__ bv)
{
    __shared__ float Xs[64][17];
    __shared__ float Ks[64][17];
    __shared__ float Vs[64][17];
    int m0 = blockIdx.x * 64, n0 = blockIdx.y * 64, b = blockIdx.z;
    int tid = threadIdx.x;
    int tn = tid & 15, tm = tid >> 4;
    float accK[4][4] = {}, accV[4][4] = {};

    for (int k0 = 0; k0 < D_; k0 += 16) {
        #pragma unroll
        for (int i = 0; i < 4; i++) {
            int e = tid + i * 256;
            int kk = e & 15, mm = e >> 4;
            Xs[mm][kk] = memory[((size_t)(m0 + mm) * BS + b) * D_ + k0 + kk];
            Ks[mm][kk] = Wk[(size_t)(n0 + mm) * D_ + k0 + kk];
            Vs[mm][kk] = Wv[(size_t)(n0 + mm) * D_ + k0 + kk];
        }
        __syncthreads();
        #pragma unroll
        for (int kk = 0; kk < 16; kk++) {
            float xv[4], kw[4], vw[4];
            #pragma unroll
            for (int i = 0; i < 4; i++) xv[i] = Xs[tm * 4 + i][kk];
            #pragma unroll
            for (int j = 0; j < 4; j++) { kw[j] = Ks[tn * 4 + j][kk]; vw[j] = Vs[tn * 4 + j][kk]; }
            #pragma unroll
            for (int i = 0; i < 4; i++)
                #pragma unroll
                for (int j = 0; j < 4; j++) {
                    accK[i][j] = fmaf(xv[i], kw[j], accK[i][j]);
                    accV[i][j] = fmaf(xv[i], vw[j], accV[i][j]);
                }
        }
        __syncthreads();
    }
    #pragma unroll
    for (int i = 0; i < 4; i++) {
        int m = m0 + tm * 4 + i;
        #pragma unroll
        for (int j = 0; j < 4; j++) {
            int n = n0 + tn * 4 + j;
            int h = n >> 6, d = n & 63;
            g_kt[(((size_t)b * NH + h) * DK + d) * MEM_ + m]  = accK[i][j] + bk[n];
            g_vp[(((size_t)b * NH + h) * MEM_ + m) * DK + d]  = accV[i][j] + bv[n];
        }
    }
}

// ---------------- phase overlays ----------------
struct QSm  { float Xs[32][133]; float Ws[4][33]; int toks[BS]; };
struct GruSm{ float Xs[2][32][133]; float Ws[2][12][33]; float red[4][64][6]; };
struct FcSm { float Xs[32][133]; float Ws[8][33]; float apv[4][BS]; int api[4][BS]; };

extern __shared__ __align__(128) unsigned char dynsm[];

__device__ __forceinline__ void grid_bar() {
    __syncthreads();
    if (threadIdx.x == 0) {
        unsigned gen = g_bar_gen;
        __threadfence();
        unsigned ticket = atomicAdd(&g_bar_count, 1u);
        if (ticket == gridDim.x - 1) {
            g_bar_count = 0;
            __threadfence();
            g_bar_gen = gen + 1;
        } else {
            while (g_bar_gen == gen) __nanosleep(32);
            __threadfence();
        }
    }
    __syncthreads();
}

// ---------------- persistent decode kernel (whole 160-step loop) ----------------
__global__ void __launch_bounds__(512, 1) decode_kernel(
    const float* __restrict__ emb,  const float* __restrict__ Wq,  const float* __restrict__ bq,
    const float* __restrict__ Wih,  const float* __restrict__ Whh,
    const float* __restrict__ bih,  const float* __restrict__ bhh,
    const float* __restrict__ Wfc,  const float* __restrict__ bfc,
    const int*   __restrict__ lens, float* __restrict__ out)
{
    const int bid = blockIdx.x;
    const int tid = threadIdx.x;

    // attention smem views
    float* qs           = (float*)(dynsm + OFF_QS);
    float (*sc)[MEM_]   = (float(*)[MEM_])(dynsm + OFF_SC);
    float (*red)[8][DK] = (float(*)[8][DK])(dynsm + OFF_RED);
    float* wred  = (float*)(dynsm + OFF_WRED);
    float* wred2 = (float*)(dynsm + OFF_WRED2);
    float* invs  = (float*)(dynsm + OFF_INVS);
    const unsigned mbar0 = s2u(dynsm + OFF_MBAR);
    const unsigned buf_s = s2u(dynsm + OFF_BUF);
    float* bufs = (float*)(dynsm + OFF_BUF);

    if (tid == 0)
        for (int j = 0; j < 4; j++) mbar_init(mbar0 + 8u * j, 1u);
    __syncthreads();

    for (int t = 0; t < TMAX; t++) {
        const float* hcur = g_h2[t & 1];
        float* hnext = g_h2[(t + 1) & 1];

        // ================= phase Q: toks + q = [emb[tok],h] @ Wq^T + bq =========
        {
            QSm& S = *(QSm*)dynsm;
            if (tid < BS) {
                int b = tid, bi = 0;
                if (t > 0) {
                    float bv = -3.4e38f;
                    for (int p = 0; p < NFC; p++) {
                        float v = g_pv[p * BS + b];
                        if (v > bv) { bv = v; bi = g_pi[p * BS + b]; }
                    }
                }
                S.toks[b] = bi;
            }
            __syncthreads();
            const int n = bid * 4 + (tid >> 7);
            const int b = tid & 127;
            float acc = 0.f;
            for (int k0 = 0; k0 < 2 * H_; k0 += 32) {
                #pragma unroll
                for (int i = 0; i < 8; i++) {
                    int e = tid + i * 512;
                    int kk = e & 31, bb = e >> 5;
                    int j = k0 + kk;
                    S.Xs[kk][bb] = (j < H_) ? emb[(size_t)S.toks[bb] * H_ + j]
                                            : hcur[bb * H_ + (j - H_)];
                }
                if (tid < 128) {
                    int row = tid >> 5, kk = tid & 31;
                    S.Ws[row][kk] = Wq[(size_t)(bid * 4 + row) * (2 * H_) + k0 + kk];
                }
                __syncthreads();
                const float* wr = S.Ws[tid >> 7];
                #pragma unroll
                for (int kk = 0; kk < 32; kk++)
                    acc = fmaf(S.Xs[kk][b], wr[kk], acc);
                __syncthreads();
            }
            g_q[b * D_ + n] = acc + bq[n];
        }
        grid_bar();

        // ================= phase ATT: block = batch; TMA-pipelined K then V =====
        {
            qs[tid] = g_q[bid * D_ + tid];
            __syncthreads();   // qs visible; all smem reads of prior phase retired

            // ---- K phase: 32 chunks of [16 d][512 m] (32 KB each) ----
            const float* ksrc = g_kt + (size_t)bid * NH * DK * MEM_;
            if (tid == 0) {
                #pragma unroll
                for (int j = 0; j < 3; j++) {
                    mbar_expect_tx(mbar0 + 8u * j, CHUNK_B);
                    tma_g2s(buf_s + j * CHUNK_B, ksrc + (size_t)j * 8192, CHUNK_B, mbar0 + 8u * j);
                }
            }
            float acc = 0.f;
            for (int c = 0; c < 32; c++) {
                if (tid == 0 && c + 3 < 32) {
                    int j = (c + 3) & 3;
                    mbar_expect_tx(mbar0 + 8u * j, CHUNK_B);
                    tma_g2s(buf_s + j * CHUNK_B, ksrc + (size_t)(c + 3) * 8192, CHUNK_B, mbar0 + 8u * j);
                }
                mbar_wait(mbar0 + 8u * (c & 3), (c >> 2) & 1);
                const float* Kc = bufs + (c & 3) * 8192;   // [16][512]
                const int h = c >> 2, d0 = (c & 3) * 16;
                if (d0 == 0) acc = 0.f;
                #pragma unroll
                for (int j = 0; j < 16; j++)
                    acc = fmaf(qs[h * DK + d0 + j], Kc[j * MEM_ + tid], acc);
                if (d0 == 48) sc[h][tid] = acc * 0.125f;
                __syncthreads();
            }

            // ---- prefetch first V chunks (buffers free), overlap with softmax ----
            const float* vsrc = g_vp + (size_t)bid * NH * MEM_ * DK;
            if (tid == 0) {
                #pragma unroll
                for (int j = 0; j < 3; j++) {
                    mbar_expect_tx(mbar0 + 8u * j, CHUNK_B);
                    tma_g2s(buf_s + j * CHUNK_B, vsrc + (size_t)j * 8192, CHUNK_B, mbar0 + 8u * j);
                }
            }

            // ---- softmax per head (64 threads/head) ----
            int h = tid >> 6, i = tid & 63;
            float mx = -3.4e38f;
            #pragma unroll
            for (int r = 0; r < 8; r++) mx = fmaxf(mx, sc[h][i + (r << 6)]);
            #pragma unroll
            for (int o = 16; o > 0; o >>= 1) mx = fmaxf(mx, __shfl_xor_sync(0xffffffffu, mx, o));
            if ((tid & 31) == 0) wred[tid >> 5] = mx;
            __syncthreads();
            float mh = fmaxf(wred[2 * h], wred[2 * h + 1]);

            float s = 0.f;
            #pragma unroll
            for (int r = 0; r < 8; r++) {
                int m = i + (r << 6);
                float e = expf(sc[h][m] - mh);
                sc[h][m] = e;
                s += e;
            }
            #pragma unroll
            for (int o = 16; o > 0; o >>= 1) s += __shfl_xor_sync(0xffffffffu, s, o);
            if ((tid & 31) == 0) wred2[tid >> 5] = s;
            __syncthreads();
            float inv = 1.f / (wred2[2 * h] + wred2[2 * h + 1]);
            if (i == 0) invs[h] = inv;
            __syncthreads();

            // ---- scores output: mean over heads (masked) ----
            {
                float sm = 0.f;
                #pragma unroll
                for (int hh = 0; hh < NH; hh++) sm += sc[hh][tid] * invs[hh];
                sm *= 0.125f;
                int run = t < lens[bid];
                out[OUT_S_OFF + ((size_t)t * BS + bid) * MEM_ + tid] = run ? sm : 0.f;
            }

            // ---- V phase: 32 chunks of [128 m][64 d]; thread = (g=tid>>6, d=tid&63)
            const int d = tid & 63, g = tid >> 6;
            float accv = 0.f;
            for (int c = 0; c < 32; c++) {
                if (tid == 0 && c + 3 < 32) {
                    int j = (c + 3) & 3;
                    mbar_expect_tx(mbar0 + 8u * j, CHUNK_B);
                    tma_g2s(buf_s + j * CHUNK_B, vsrc + (size_t)(c + 3) * 8192, CHUNK_B, mbar0 + 8u * j);
                }
                mbar_wait(mbar0 + 8u * (c & 3), (c >> 2) & 1);
                const float* Vc = bufs + (c & 3) * 8192;   // [128][64]
                const int vh = c >> 2, m0 = (c & 3) * 128;
                if (m0 == 0) accv = 0.f;
                const float* ph = &sc[vh][m0];
                #pragma unroll
                for (int k = 0; k < 16; k++) {
                    int ml = g * 16 + k;
                    accv = fmaf(ph[ml], Vc[ml * 64 + d], accv);
                }
                if (m0 == 384) red[vh][g][d] = accv;
                __syncthreads();
            }
            // final reduce over the 8 m-groups
            {
                int rh = tid >> 6, rd = tid & 63;
                float sum = 0.f;
                #pragma unroll
                for (int gg = 0; gg < 8; gg++) sum += red[rh][gg][rd];
                g_ctx[bid * D_ + rh * DK + rd] = sum * invs[rh];
            }
        }
        grid_bar();

        // ================= phase GRU (gate-triple tiling, fused activation) ======
        {
            GruSm& S = *(GruSm*)dynsm;
            const int j0 = bid * 4;
            const int kh = tid >> 8;
            const int r  = tid & 255;
            const int jj = r >> 6, bp = r & 63, b0 = bp * 2;
            const float* xsrc = kh ? hcur : g_ctx;
            const float* Wsrc = kh ? Whh  : Wih;
            float a[3][2] = {};
            for (int k0 = 0; k0 < H_; k0 += 32) {
                #pragma unroll
                for (int i = 0; i < 16; i++) {
                    int e = r + i * 256;
                    int kk = e & 31, bb = e >> 5;
                    S.Xs[kh][kk][bb] = xsrc[bb * H_ + k0 + kk];
                }
                #pragma unroll
                for (int i = 0; i < 2; i++) {
                    int e = r + i * 256;
                    if (e < 384) {
                        int row = e >> 5, kk = e & 31;
                        int g = row >> 2, jr = row & 3;
                        S.Ws[kh][row][kk] = Wsrc[((size_t)g * H_ + j0 + jr) * H_ + k0 + kk];
                    }
                }
                __syncthreads();
                #pragma unroll
                for (int kk = 0; kk < 32; kk++) {
                    float x0 = S.Xs[kh][kk][b0];
                    float x1 = S.Xs[kh][kk][b0 + 1];
                    #pragma unroll
                    for (int g = 0; g < 3; g++) {
                        float w = S.Ws[kh][g * 4 + jj][kk];
                        a[g][0] = fmaf(x0, w, a[g][0]);
                        a[g][1] = fmaf(x1, w, a[g][1]);
                    }
                }
                __syncthreads();
            }
            if (kh == 1) {
                #pragma unroll
                for (int g = 0; g < 3; g++) {
                    S.red[jj][bp][g * 2]     = a[g][0];
                    S.red[jj][bp][g * 2 + 1] = a[g][1];
                }
            }
            __syncthreads();
            if (kh == 0) {
                int j = j0 + jj;
                float bir = bih[j], biz = bih[j + H_], bin_ = bih[j + 2 * H_];
                float bhr = bhh[j], bhz = bhh[j + H_], bhn = bhh[j + 2 * H_];
                #pragma unroll
                for (int ib = 0; ib < 2; ib++) {
                    int b = b0 + ib;
                    float gir = a[0][ib] + bir;
                    float giz = a[1][ib] + biz;
                    float gin = a[2][ib] + bin_;
                    float ghr = S.red[jj][bp][0 * 2 + ib] + bhr;
                    float ghz = S.red[jj][bp][1 * 2 + ib] + bhz;
                    float ghn = S.red[jj][bp][2 * 2 + ib] + bhn;
                    float rr = sigmoidf_(gir + ghr);
                    float zz = sigmoidf_(giz + ghz);
                    float nn = tanhf(gin + rr * ghn);
                    float hold = hcur[b * H_ + j];
                    float hn = (1.f - zz) * nn + zz * hold;
                    hnext[b * H_ + j] = hn;
                    int run = t < lens[b];
                    out[OUT_H_OFF + ((size_t)t * BS + b) * H_ + j] = run ? hn : 0.f;
                }
            }
        }
        grid_bar();

        // ================= phase FC (+ partial argmax) ===========================
        if (bid < NFC) {
            FcSm& S = *(FcSm*)dynsm;
            const int n0 = bid * 8;
            const int tn = tid >> 7;
            const int b  = tid & 127;
            float acc0 = 0.f, acc1 = 0.f;
            for (int k0 = 0; k0 < H_; k0 += 32) {
                #pragma unroll
                for (int i = 0; i < 8; i++) {
                    int e = tid + i * 512;
                    int kk = e & 31, bb = e >> 5;
                    S.Xs[kk][bb] = hnext[bb * H_ + k0 + kk];
                }
                if (tid < 256) {
                    int row = tid >> 5, kk = tid & 31;
                    S.Ws[row][kk] = Wfc[(size_t)(n0 + row) * H_ + k0 + kk];
                }
                __syncthreads();
                const float* w0 = S.Ws[tn * 2];
                const float* w1 = S.Ws[tn * 2 + 1];
                #pragma unroll
                for (int kk = 0; kk < 32; kk++) {
                    float x = S.Xs[kk][b];
                    acc0 = fmaf(x, w0[kk], acc0);
                    acc1 = fmaf(x, w1[kk], acc1);
                }
                __syncthreads();
            }
            int na = n0 + tn * 2, nb = na + 1;
            float v0 = acc0 + bfc[na];
            float v1 = acc1 + bfc[nb];
            int run = t < lens[b];
            size_t ob = ((size_t)t * BS + b) * V_;
            out[ob + na] = run ? v0 : 0.f;
            out[ob + nb] = run ? v1 : 0.f;
            float lv = v0; int li = na;
            if (v1 > lv) { lv = v1; li = nb; }
            S.apv[tn][b] = lv;
            S.api[tn][b] = li;
            __syncthreads();
            if (tn == 0) {
                float bv = S.apv[0][b]; int bi = S.api[0][b];
                #pragma unroll
                for (int p = 1; p < 4; p++) {
                    float v = S.apv[p][b];
                    if (v > bv) { bv = v; bi = S.api[p][b]; }
                }
                g_pv[bid * BS + b] = bv;
                g_pi[bid * BS + b] = bi;
            }
        }
        grid_bar();
    }
}

// ---------------- launch ----------------
extern "C" void kernel_launch(void* const* d_in, const int* in_sizes, int n_in,
                              void* d_out, int out_size)
{
    const float* memory = (const float*)d_in[0];
    const float* emb    = (const float*)d_in[1];
    const float* Wq     = (const float*)d_in[2];
    const float* bq     = (const float*)d_in[3];
    const float* Wk     = (const float*)d_in[4];
    const float* bk     = (const float*)d_in[5];
    const float* Wv     = (const float*)d_in[6];
    const float* bv     = (const float*)d_in[7];
    const float* Wih    = (const float*)d_in[8];
    const float* Whh    = (const float*)d_in[9];
    const float* bih    = (const float*)d_in[10];
    const float* bhh    = (const float*)d_in[11];
    const float* Wfc    = (const float*)d_in[12];
    const float* bfc    = (const float*)d_in[13];
    const int*   lens   = (const int*)d_in[14];
    float* out = (float*)d_out;

    // Host-side, non-stream API: idempotent, called unconditionally (no static
    // guards allowed). Legal alongside graph capture since it is not a stream op.
    cudaFuncSetAttribute(decode_kernel, cudaFuncAttributeMaxDynamicSharedMemorySize, SMEM_TOTAL);

    init_kernel<<<128, 256>>>();
    kvproj_kernel<<<dim3(MEM_ / 64, D_ / 64, BS), 256>>>(memory, Wk, bk, Wv, bv);
    decode_kernel<<<NBLK, 512, SMEM_TOTAL>>>(emb, Wq, bq, Wih, Whh, bih, bhh, Wfc, bfc, lens, out);
}